// round 17
// baseline (speedup 1.0000x reference)
#include <cuda_runtime.h>
#include <cstdint>

#define CH_IN 32
#define CH_Y  16
#define IMG_H 256
#define IMG_W 256
#define NB    16
#define CHS   (IMG_H * IMG_W)   // channel stride (elements)
#define CHS4  (CHS / 4)
#define CHS2  (CHS / 2)
#define NT    128               // thread = (t6 in [0,64), H = tid>>6 o-half)
#define ROWB  (IMG_W * 4)       // bytes per channel strip (1KB)

union F2U { float2 f; uint64_t u; };

// sm_103a packed dual-fp32 ops
__device__ __forceinline__ void fma2(uint64_t& d, uint64_t a, uint64_t b) {
    asm("fma.rn.f32x2 %0, %1, %2, %0;" : "+l"(d) : "l"(a), "l"(b));
}
__device__ __forceinline__ uint64_t mul2(uint64_t a, uint64_t b) {
    uint64_t d; asm("mul.rn.f32x2 %0, %1, %2;" : "=l"(d) : "l"(a), "l"(b)); return d;
}
__device__ __forceinline__ uint64_t add2(uint64_t a, uint64_t b) {
    uint64_t d; asm("add.rn.f32x2 %0, %1, %2;" : "=l"(d) : "l"(a), "l"(b)); return d;
}
__device__ __forceinline__ uint64_t dup2(float x) {
    uint64_t d; asm("mov.b64 %0, {%1, %1};" : "=l"(d) : "f"(x)); return d;
}
__device__ __forceinline__ uint64_t pack2(float lo, float hi) {
    uint64_t d; asm("mov.b64 %0, {%1, %2};" : "=l"(d) : "f"(lo), "f"(hi)); return d;
}

// TMA / mbarrier primitives (1D bulk)
__device__ __forceinline__ void mbar_init(uint32_t mbar, uint32_t cnt) {
    asm volatile("mbarrier.init.shared.b64 [%0], %1;" :: "r"(mbar), "r"(cnt) : "memory");
}
__device__ __forceinline__ void mbar_expect(uint32_t mbar, uint32_t bytes) {
    asm volatile("mbarrier.arrive.expect_tx.shared.b64 _, [%0], %1;"
                 :: "r"(mbar), "r"(bytes) : "memory");
}
__device__ __forceinline__ void mbar_wait(uint32_t mbar, uint32_t parity) {
    asm volatile(
        "{\n\t.reg .pred P;\n"
        "WL_%=:\n\t"
        "mbarrier.try_wait.parity.shared.b64 P, [%0], %1, 0x989680;\n\t"
        "@P bra WD_%=;\n\t"
        "bra WL_%=;\n"
        "WD_%=:\n\t}"
        :: "r"(mbar), "r"(parity) : "memory");
}
__device__ __forceinline__ void bulk_ld(uint32_t sdst, const void* gsrc,
                                        uint32_t bytes, uint32_t mbar) {
    asm volatile("cp.async.bulk.shared::cta.global.mbarrier::complete_tx::bytes "
                 "[%0], [%1], %2, [%3];"
                 :: "r"(sdst), "l"(gsrc), "r"(bytes), "r"(mbar) : "memory");
}

// smem carve (bytes): p staging (reused as ybuf) + weights (~41KB, 4 blocks/SM)
#define SM_P   0                 // p row staging 32KB; ybuf overlay (16KB used)
#define SM_WQ  32768             // wqT 2KB
#define SM_WK  (SM_WQ + 2048)
#define SM_WV  (SM_WK + 2048)
#define SM_WY  (SM_WV + 2048)    // wy 2KB
#define SM_BQ  (SM_WY + 2048)
#define SM_BK  (SM_BQ + 64)
#define SM_BV  (SM_BK + 64)
#define SM_BY  (SM_BV + 64)
#define SM_RED (SM_BY + 128)     // 4 warps x 4 u64
#define SM_MB  (SM_RED + 256)    // mbarrier
#define SM_TOT (SM_MB + 64)

// 4 px/thread + o-split: thread (t6, H) owns pixels 4*t6..4*t6+3 and output
// channels o in [8H, 8H+8). Warps are H-uniform (H = tid>>6): weight LDS per
// warp halves vs R16 while px amortization halves it again. TMA p-staging,
// c streamed with concat write-through, pixel-split output conv via smem
// y-exchange overlaid on the dead p region.
__global__ void __launch_bounds__(NT, 4) cross_attn_kernel(
    const float* __restrict__ cin, const float* __restrict__ pin,
    const float* __restrict__ Wq,  const float* __restrict__ bq,
    const float* __restrict__ Wk,  const float* __restrict__ bk,
    const float* __restrict__ Wv,  const float* __restrict__ bv,
    const float* __restrict__ Wy,  const float* __restrict__ by,
    float* __restrict__ out)
{
    extern __shared__ __align__(16) char smraw[];
    float2*   wqT  = (float2*)(smraw + SM_WQ);   // [c][o2] natural o-pairs
    float2*   wkT  = (float2*)(smraw + SM_WK);
    float2*   wvT  = (float2*)(smraw + SM_WV);
    float4*   wy_s = (float4*)(smraw + SM_WY);
    float2*   bq2  = (float2*)(smraw + SM_BQ);
    float2*   bk2  = (float2*)(smraw + SM_BK);
    float2*   bv2  = (float2*)(smraw + SM_BV);
    float*    by_s = (float*) (smraw + SM_BY);
    uint64_t* red  = (uint64_t*)(smraw + SM_RED);   // [warp][olp]
    const uint32_t smbase = (uint32_t)__cvta_generic_to_shared(smraw);
    const uint32_t mbar   = smbase + SM_MB;

    const int tid = threadIdx.x;
    const int t6  = tid & 63;         // pixel group (float4 slot in row)
    const int H   = tid >> 6;         // o-half; warp-uniform
    const int h = blockIdx.x & (IMG_H - 1);
    const int b = blockIdx.x >> 8;
    const size_t base = (size_t)b * CH_IN * CHS + (size_t)h * IMG_W;

    // ---- kick off TMA p-load first so it overlaps weight setup ----
    if (tid == 0) {
        mbar_init(mbar, 1);
        asm volatile("fence.proxy.async.shared::cta;" ::: "memory");
        mbar_expect(mbar, CH_IN * ROWB);
#pragma unroll 4
        for (int ch = 0; ch < CH_IN; ch++)
            bulk_ld(smbase + SM_P + ch * ROWB, pin + base + (size_t)ch * CHS,
                    ROWB, mbar);
    }

    // ---- weight setup (transpose to [c][o2] pair layout) ----
#pragma unroll
    for (int s = 0; s < 2; s++) {
        int i = tid * 2 + s;                     // 0..255
        int c = i >> 3, o2 = i & 7;
        wqT[i] = make_float2(Wq[(2*o2)*CH_IN + c], Wq[(2*o2+1)*CH_IN + c]);
        wkT[i] = make_float2(Wk[(2*o2)*CH_IN + c], Wk[(2*o2+1)*CH_IN + c]);
        wvT[i] = make_float2(Wv[(2*o2)*CH_IN + c], Wv[(2*o2+1)*CH_IN + c]);
    }
    wy_s[tid] = ((const float4*)Wy)[tid];
    if (tid < 8) {
        bq2[tid] = make_float2(bq[2*tid], bq[2*tid+1]);
        bk2[tid] = make_float2(bk[2*tid], bk[2*tid+1]);
        bv2[tid] = make_float2(bv[2*tid], bv[2*tid+1]);
    }
    if (tid < CH_IN) by_s[tid] = by[tid];
    __syncthreads();
    mbar_wait(mbar, 0);                          // p row staged

    const float4* cg  = (const float4*)(cin + base);       // + ch*CHS4 + t6
    const float4* sp4 = (const float4*)(smraw + SM_P);     // + ch*64 + t6
    float4* oyg = (float4*)(out + (size_t)b * 2 * CH_IN * CHS + (size_t)h * IMG_W);
    float4* ocg = oyg + (size_t)CH_IN * CHS4;              // concat(c) half

    // ---------------- q,k projection (my o-half, 4 px) ----------------
    uint64_t q[4][4], k[4][4];        // [px][local o-pair]
#pragma unroll
    for (int ol = 0; ol < 4; ol++) {
        F2U tq; tq.f = bq2[H * 4 + ol];
        F2U tk; tk.f = bk2[H * 4 + ol];
#pragma unroll
        for (int px = 0; px < 4; px++) { q[px][ol] = tq.u; k[px][ol] = tk.u; }
    }

#pragma unroll
    for (int c2 = 0; c2 < CH_IN / 2; c2++) {     // 2 channels per step
        float4 cf[2], pf[2];
#pragma unroll
        for (int j = 0; j < 2; j++) {
            int ch = c2 * 2 + j;
            cf[j] = cg[(size_t)ch * CHS4 + t6];  // DRAM/L2 stream
            pf[j] = sp4[ch * 64 + t6];
        }
#pragma unroll
        for (int j = 0; j < 2; j++)              // concat write-through
            ocg[(size_t)(c2 * 2 + j) * CHS4 + t6] = cf[j];
#pragma unroll
        for (int j = 0; j < 2; j++) {
            const int ch = c2 * 2 + j;
            const ulonglong2* wq2 = (const ulonglong2*)&wqT[ch * 8 + H * 4];
            const ulonglong2* wk2 = (const ulonglong2*)&wkT[ch * 8 + H * 4];
            uint64_t cd[4] = { dup2(cf[j].x), dup2(cf[j].y),
                               dup2(cf[j].z), dup2(cf[j].w) };
            uint64_t pd[4] = { dup2(pf[j].x), dup2(pf[j].y),
                               dup2(pf[j].z), dup2(pf[j].w) };
#pragma unroll
            for (int m = 0; m < 2; m++) {        // 2 local o-pairs per LDS.128
                ulonglong2 a = wq2[m];
                ulonglong2 bm = wk2[m];
#pragma unroll
                for (int px = 0; px < 4; px++) {
                    fma2(q[px][2*m+0], a.x,  cd[px]);
                    fma2(q[px][2*m+1], a.y,  cd[px]);
                    fma2(k[px][2*m+0], bm.x, pd[px]);
                    fma2(k[px][2*m+1], bm.y, pd[px]);
                }
            }
        }
    }

    // exp(q*k). No max-subtraction: |q*k| O(1..10); fp32 exp safe, identical
    // after normalization.
    uint64_t e[4][4];
#pragma unroll
    for (int px = 0; px < 4; px++)
#pragma unroll
        for (int ol = 0; ol < 4; ol++) {
            F2U pr; pr.u = mul2(q[px][ol], k[px][ol]);
            e[px][ol] = pack2(__expf(pr.f.x), __expf(pr.f.y));
        }

    // -------- softmax over width: warps of my H cover all 256 px --------
    const int lane = tid & 31;
    const int wrp  = tid >> 5;        // warps {2H, 2H+1} hold my o-half
#pragma unroll
    for (int ol = 0; ol < 4; ol++) {
        uint64_t s = add2(add2(e[0][ol], e[1][ol]), add2(e[2][ol], e[3][ol]));
#pragma unroll
        for (int d = 16; d > 0; d >>= 1)
            s = add2(s, __shfl_xor_sync(0xffffffffu, (unsigned long long)s, d));
        if (lane == 0) red[wrp * 4 + ol] = s;
    }
    __syncthreads();

#pragma unroll
    for (int ol = 0; ol < 4; ol++) {
        F2U tot; tot.u = add2(red[(2*H+0) * 4 + ol], red[(2*H+1) * 4 + ol]);
        uint64_t inv = pack2(__frcp_rn(tot.f.x), __frcp_rn(tot.f.y));
#pragma unroll
        for (int px = 0; px < 4; px++)
            e[px][ol] = mul2(e[px][ol], inv);    // fold 1/sum into e
    }

    // ---------------- v projection (my o-half), y folded in ----------------
    {
        uint64_t v[4][4];
#pragma unroll
        for (int ol = 0; ol < 4; ol++) {
            F2U tv; tv.f = bv2[H * 4 + ol];
#pragma unroll
            for (int px = 0; px < 4; px++) v[px][ol] = tv.u;
        }
#pragma unroll
        for (int c2 = 0; c2 < CH_IN / 2; c2++) {
            float4 pf[2];
#pragma unroll
            for (int j = 0; j < 2; j++)
                pf[j] = sp4[(c2 * 2 + j) * 64 + t6];
#pragma unroll
            for (int j = 0; j < 2; j++) {
                const int ch = c2 * 2 + j;
                const ulonglong2* wv2 = (const ulonglong2*)&wvT[ch * 8 + H * 4];
                uint64_t pd[4] = { dup2(pf[j].x), dup2(pf[j].y),
                                   dup2(pf[j].z), dup2(pf[j].w) };
#pragma unroll
                for (int m = 0; m < 2; m++) {
                    ulonglong2 a = wv2[m];
#pragma unroll
                    for (int px = 0; px < 4; px++) {
                        fma2(v[px][2*m+0], a.x, pd[px]);
                        fma2(v[px][2*m+1], a.y, pd[px]);
                    }
                }
            }
        }
#pragma unroll
        for (int px = 0; px < 4; px++)
#pragma unroll
            for (int ol = 0; ol < 4; ol++)
                e[px][ol] = mul2(e[px][ol], v[px][ol]);   // y = softmax * v
    }

    // -------- y exchange via smem overlay on dead p region --------
    __syncthreads();                  // all p reads complete before overwrite
    uint64_t* ybuf = (uint64_t*)(smraw + SM_P);   // [(o2*4+px)][t6], 16KB
#pragma unroll
    for (int ol = 0; ol < 4; ol++)
#pragma unroll
        for (int px = 0; px < 4; px++)
            ybuf[((H * 4 + ol) * 4 + px) * 64 + t6] = e[px][ol];
    __syncthreads();

    // conv pixels for this thread: px 2H, 2H+1 of group t6
    uint64_t ya[2][8];                // [pxl][global o2]
#pragma unroll
    for (int o2 = 0; o2 < 8; o2++) {
        ya[0][o2] = ybuf[(o2 * 4 + 2 * H + 0) * 64 + t6];
        ya[1][o2] = ybuf[(o2 * 4 + 2 * H + 1) * 64 + t6];
    }

    // ---------------- output conv1x1: all 32 ic, my 2 px ----------------
    float2* oy2 = (float2*)(out + (size_t)b * 2 * CH_IN * CHS + (size_t)h * IMG_W);
    const ulonglong2* wyu2 = (const ulonglong2*)wy_s;    // 4 per ic (broadcast)
#pragma unroll
    for (int ic = 0; ic < CH_IN; ic++) {
        uint64_t acc0 = pack2(by_s[ic], 0.f);
        uint64_t acc1 = acc0;
#pragma unroll
        for (int m = 0; m < 4; m++) {
            ulonglong2 w = wyu2[ic * 4 + m];             // o2 (2m, 2m+1)
            fma2(acc0, w.x, ya[0][2*m+0]); fma2(acc0, w.y, ya[0][2*m+1]);
            fma2(acc1, w.x, ya[1][2*m+0]); fma2(acc1, w.y, ya[1][2*m+1]);
        }
        F2U r0, r1; r0.u = acc0; r1.u = acc1;
        oy2[(size_t)ic * CHS2 + 2 * t6 + H] = make_float2(r0.f.x + r0.f.y,
                                                          r1.f.x + r1.f.y);
    }
}

extern "C" void kernel_launch(void* const* d_in, const int* in_sizes, int n_in,
                              void* d_out, int out_size)
{
    cudaFuncSetAttribute(cross_attn_kernel,
                         cudaFuncAttributeMaxDynamicSharedMemorySize, SM_TOT);
    cross_attn_kernel<<<NB * IMG_H, NT, SM_TOT>>>(
        (const float*)d_in[0],  // c
        (const float*)d_in[1],  // p
        (const float*)d_in[2],  // Wq
        (const float*)d_in[3],  // bq
        (const float*)d_in[4],  // Wk
        (const float*)d_in[5],  // bk
        (const float*)d_in[6],  // Wv
        (const float*)d_in[7],  // bv
        (const float*)d_in[8],  // Wy
        (const float*)d_in[9],  // by
        (float*)d_out);
}